// round 6
// baseline (speedup 1.0000x reference)
#include <cuda_runtime.h>
#include <math.h>

// Problem constants
#define BB   2
#define SS   2048
#define DDIM 1024
#define HH   16
#define DK   64
#define FFD  4096
#define MTOT (BB*SS)   // 4096 rows

// ---------------------------------------------------------------------------
// Scratch buffers (device globals; no runtime allocation allowed)
// ---------------------------------------------------------------------------
__device__ float g_xn [MTOT*DDIM];
__device__ float g_q  [MTOT*DDIM];
__device__ float g_k  [MTOT*DDIM];
__device__ float g_v  [MTOT*DDIM];
__device__ float g_ctx[MTOT*DDIM];
__device__ float g_h  [MTOT*DDIM];
__device__ float g_hn [MTOT*DDIM];
__device__ float g_ff [MTOT*FFD];

// ---------------------------------------------------------------------------
// LayerNorm (faithful: unbiased std, denom = sqrt(std + eps))
// one block per row, 256 threads, row length 1024 (= 256 float4)
// ---------------------------------------------------------------------------
__global__ __launch_bounds__(256) void ln_kernel(
    const float* __restrict__ x, const float* __restrict__ alpha,
    const float* __restrict__ beta, float* __restrict__ y)
{
    const int row = blockIdx.x;
    const float4* xr = reinterpret_cast<const float4*>(x + (size_t)row * DDIM);
    float4 vv = xr[threadIdx.x];
    float s  = vv.x + vv.y + vv.z + vv.w;
    float s2 = vv.x*vv.x + vv.y*vv.y + vv.z*vv.z + vv.w*vv.w;

    __shared__ float red0[8], red1[8];
    #pragma unroll
    for (int o = 16; o; o >>= 1) {
        s  += __shfl_xor_sync(0xffffffffu, s,  o);
        s2 += __shfl_xor_sync(0xffffffffu, s2, o);
    }
    const int warp = threadIdx.x >> 5, lane = threadIdx.x & 31;
    if (lane == 0) { red0[warp] = s; red1[warp] = s2; }
    __syncthreads();
    if (threadIdx.x == 0) {
        float t = 0.f, t2 = 0.f;
        #pragma unroll
        for (int i = 0; i < 8; i++) { t += red0[i]; t2 += red1[i]; }
        red0[0] = t; red1[0] = t2;
    }
    __syncthreads();
    s = red0[0]; s2 = red1[0];

    const float mean = s * (1.0f / DDIM);
    const float var  = fmaxf(0.f, (s2 - s * mean) * (1.0f / (DDIM - 1)));  // unbiased
    const float stdv = sqrtf(var);
    const float inv  = 1.0f / sqrtf(stdv + 1e-6f);   // sqrt(std + eps) !
    const float a0 = alpha[0], b0 = beta[0];

    float4 o;
    o.x = a0 * (vv.x - mean) * inv + b0;
    o.y = a0 * (vv.y - mean) * inv + b0;
    o.z = a0 * (vv.z - mean) * inv + b0;
    o.w = a0 * (vv.w - mean) * inv + b0;
    reinterpret_cast<float4*>(y + (size_t)row * DDIM)[threadIdx.x] = o;
}

// ---------------------------------------------------------------------------
// SGEMM (NT): C[M,N] = A[M,K] * W[N,K]^T + bias[N]  (+optional relu / +res)
// 128x128x16 tiles, 256 threads, 8x8 micro-tile (split 4+4 for conflict-free
// float4 smem reads). M,N multiples of 128; K multiple of 16 (always true here).
// ---------------------------------------------------------------------------
__global__ __launch_bounds__(256, 2) void gemm_nt(
    const float* __restrict__ A, const float* __restrict__ W,
    const float* __restrict__ bias, const float* __restrict__ res,
    float* __restrict__ C, int M, int N, int K, int relu)
{
    __shared__ float As[16][128];
    __shared__ float Bs[16][128];

    const int tid = threadIdx.x;
    const int tx = tid & 15, ty = tid >> 4;
    const int m0 = blockIdx.y * 128, n0 = blockIdx.x * 128;

    float acc[8][8];
    #pragma unroll
    for (int i = 0; i < 8; i++)
        #pragma unroll
        for (int j = 0; j < 8; j++) acc[i][j] = 0.f;

    for (int k0 = 0; k0 < K; k0 += 16) {
        #pragma unroll
        for (int u = 0; u < 2; u++) {
            const int f = tid + u * 256;          // 0..511 float4 slots
            const int r = f >> 2, kq = (f & 3) << 2;
            float4 a4 = *reinterpret_cast<const float4*>(A + (size_t)(m0 + r) * K + k0 + kq);
            As[kq+0][r] = a4.x; As[kq+1][r] = a4.y; As[kq+2][r] = a4.z; As[kq+3][r] = a4.w;
            float4 b4 = *reinterpret_cast<const float4*>(W + (size_t)(n0 + r) * K + k0 + kq);
            Bs[kq+0][r] = b4.x; Bs[kq+1][r] = b4.y; Bs[kq+2][r] = b4.z; Bs[kq+3][r] = b4.w;
        }
        __syncthreads();
        #pragma unroll
        for (int kk = 0; kk < 16; kk++) {
            float a[8], b[8];
            *reinterpret_cast<float4*>(&a[0]) = *reinterpret_cast<const float4*>(&As[kk][ty*4]);
            *reinterpret_cast<float4*>(&a[4]) = *reinterpret_cast<const float4*>(&As[kk][64 + ty*4]);
            *reinterpret_cast<float4*>(&b[0]) = *reinterpret_cast<const float4*>(&Bs[kk][tx*4]);
            *reinterpret_cast<float4*>(&b[4]) = *reinterpret_cast<const float4*>(&Bs[kk][64 + tx*4]);
            #pragma unroll
            for (int i = 0; i < 8; i++)
                #pragma unroll
                for (int j = 0; j < 8; j++)
                    acc[i][j] = fmaf(a[i], b[j], acc[i][j]);
        }
        __syncthreads();
    }

    const float4 bi0 = *reinterpret_cast<const float4*>(bias + n0 + tx*4);
    const float4 bi1 = *reinterpret_cast<const float4*>(bias + n0 + 64 + tx*4);

    #pragma unroll
    for (int i = 0; i < 8; i++) {
        const int rr = (i < 4) ? (ty*4 + i) : (64 + ty*4 + (i-4));
        const size_t base = (size_t)(m0 + rr) * N + n0;
        float4 c0, c1;
        c0.x = acc[i][0] + bi0.x; c0.y = acc[i][1] + bi0.y;
        c0.z = acc[i][2] + bi0.z; c0.w = acc[i][3] + bi0.w;
        c1.x = acc[i][4] + bi1.x; c1.y = acc[i][5] + bi1.y;
        c1.z = acc[i][6] + bi1.z; c1.w = acc[i][7] + bi1.w;
        if (relu) {
            c0.x = fmaxf(c0.x, 0.f); c0.y = fmaxf(c0.y, 0.f);
            c0.z = fmaxf(c0.z, 0.f); c0.w = fmaxf(c0.w, 0.f);
            c1.x = fmaxf(c1.x, 0.f); c1.y = fmaxf(c1.y, 0.f);
            c1.z = fmaxf(c1.z, 0.f); c1.w = fmaxf(c1.w, 0.f);
        }
        if (res) {
            float4 r0 = *reinterpret_cast<const float4*>(res + base + tx*4);
            float4 r1 = *reinterpret_cast<const float4*>(res + base + 64 + tx*4);
            c0.x += r0.x; c0.y += r0.y; c0.z += r0.z; c0.w += r0.w;
            c1.x += r1.x; c1.y += r1.y; c1.z += r1.z; c1.w += r1.w;
        }
        *reinterpret_cast<float4*>(C + base + tx*4)      = c0;
        *reinterpret_cast<float4*>(C + base + 64 + tx*4) = c1;
    }
}

// ---------------------------------------------------------------------------
// Flash attention, fp32. Br=Bc=64, DK=64, 256 threads (16x16, 4x4 micro-tile).
// K tile stored transposed with XOR swizzle (conflict-free transposed fill);
// P tile aliases the K tile (saves smem -> exactly 48KB static).
// ---------------------------------------------------------------------------
__global__ __launch_bounds__(256, 2) void attn_kernel(
    const float* __restrict__ Q, const float* __restrict__ K,
    const float* __restrict__ V, float* __restrict__ O)
{
    __shared__ float Qs[64][64];
    __shared__ float Vs[64][64];
    __shared__ float KP[64][64];   // K^T (swizzled) during S-gemm; P afterwards

    const int tid = threadIdx.x;
    const int tx = tid & 15, ty = tid >> 4;
    const int qb = blockIdx.x;        // query block 0..31
    const int bh = blockIdx.y;        // 0..31
    const int b  = bh >> 4, h = bh & 15;

    const size_t baseQ  = ((size_t)b * SS + (size_t)qb * 64) * DDIM + (size_t)h * DK;
    const size_t baseKV = (size_t)b * SS * DDIM + (size_t)h * DK;

    // Load Q tile (64 rows x 64 d), float4
    #pragma unroll
    for (int u = 0; u < 4; u++) {
        const int f = tid + u * 256;            // 0..1023 float4 slots
        const int r = f >> 4, cq = (f & 15) << 2;
        *reinterpret_cast<float4*>(&Qs[r][cq]) =
            *reinterpret_cast<const float4*>(Q + baseQ + (size_t)r * DDIM + cq);
    }

    float Oacc[4][4];
    float mrun[4], lrun[4];
    #pragma unroll
    for (int i = 0; i < 4; i++) {
        mrun[i] = -INFINITY; lrun[i] = 0.f;
        #pragma unroll
        for (int j = 0; j < 4; j++) Oacc[i][j] = 0.f;
    }

    for (int kv0 = 0; kv0 < SS; kv0 += 64) {
        __syncthreads();   // prev iteration done with Vs / KP(P)
        // Fill K^T (swizzled) and V
        #pragma unroll
        for (int u = 0; u < 4; u++) {
            const int f = tid + u * 256;
            const int n = f >> 4, cq = (f & 15) << 2;
            float4 kt = *reinterpret_cast<const float4*>(K + baseKV + (size_t)(kv0 + n) * DDIM + cq);
            KP[cq+0][n ^ ((cq+0) & 31)] = kt.x;
            KP[cq+1][n ^ ((cq+1) & 31)] = kt.y;
            KP[cq+2][n ^ ((cq+2) & 31)] = kt.z;
            KP[cq+3][n ^ ((cq+3) & 31)] = kt.w;
            *reinterpret_cast<float4*>(&Vs[n][cq]) =
                *reinterpret_cast<const float4*>(V + baseKV + (size_t)(kv0 + n) * DDIM + cq);
        }
        __syncthreads();

        // S = Q K^T  (contraction over d=64)
        float Sv[4][4];
        #pragma unroll
        for (int i = 0; i < 4; i++)
            #pragma unroll
            for (int j = 0; j < 4; j++) Sv[i][j] = 0.f;

        #pragma unroll 8
        for (int c = 0; c < 64; c++) {
            const int sw = c & 31, t4 = tx * 4;
            float a0 = Qs[ty*4+0][c], a1 = Qs[ty*4+1][c];
            float a2 = Qs[ty*4+2][c], a3 = Qs[ty*4+3][c];
            float b0 = KP[c][(t4+0) ^ sw], b1 = KP[c][(t4+1) ^ sw];
            float b2 = KP[c][(t4+2) ^ sw], b3 = KP[c][(t4+3) ^ sw];
            Sv[0][0] = fmaf(a0,b0,Sv[0][0]); Sv[0][1] = fmaf(a0,b1,Sv[0][1]);
            Sv[0][2] = fmaf(a0,b2,Sv[0][2]); Sv[0][3] = fmaf(a0,b3,Sv[0][3]);
            Sv[1][0] = fmaf(a1,b0,Sv[1][0]); Sv[1][1] = fmaf(a1,b1,Sv[1][1]);
            Sv[1][2] = fmaf(a1,b2,Sv[1][2]); Sv[1][3] = fmaf(a1,b3,Sv[1][3]);
            Sv[2][0] = fmaf(a2,b0,Sv[2][0]); Sv[2][1] = fmaf(a2,b1,Sv[2][1]);
            Sv[2][2] = fmaf(a2,b2,Sv[2][2]); Sv[2][3] = fmaf(a2,b3,Sv[2][3]);
            Sv[3][0] = fmaf(a3,b0,Sv[3][0]); Sv[3][1] = fmaf(a3,b1,Sv[3][1]);
            Sv[3][2] = fmaf(a3,b2,Sv[3][2]); Sv[3][3] = fmaf(a3,b3,Sv[3][3]);
        }

        // Online softmax (rows owned by (ty,i); reduce over tx via shfl)
        #pragma unroll
        for (int i = 0; i < 4; i++) {
            float rm = -INFINITY;
            #pragma unroll
            for (int j = 0; j < 4; j++) {
                Sv[i][j] *= 0.125f;                 // 1/sqrt(64)
                rm = fmaxf(rm, Sv[i][j]);
            }
            #pragma unroll
            for (int o = 8; o; o >>= 1)
                rm = fmaxf(rm, __shfl_xor_sync(0xffffffffu, rm, o));
            const float mn = fmaxf(mrun[i], rm);
            const float corr = __expf(mrun[i] - mn);   // 0 on first tile
            mrun[i] = mn;
            float rs = 0.f;
            #pragma unroll
            for (int j = 0; j < 4; j++) {
                const float p = __expf(Sv[i][j] - mn);
                Sv[i][j] = p; rs += p;
            }
            #pragma unroll
            for (int o = 8; o; o >>= 1)
                rs += __shfl_xor_sync(0xffffffffu, rs, o);
            lrun[i] = lrun[i] * corr + rs;
            #pragma unroll
            for (int j = 0; j < 4; j++) Oacc[i][j] *= corr;
        }

        __syncthreads();   // everyone done reading KP as K^T
        #pragma unroll
        for (int i = 0; i < 4; i++)
            #pragma unroll
            for (int j = 0; j < 4; j++)
                KP[ty*4 + i][tx*4 + j] = Sv[i][j];   // P tile (plain layout)
        __syncthreads();

        // O += P V  (contraction over kv c=64)
        #pragma unroll 8
        for (int c = 0; c < 64; c++) {
            float p0 = KP[ty*4+0][c], p1 = KP[ty*4+1][c];
            float p2 = KP[ty*4+2][c], p3 = KP[ty*4+3][c];
            float4 bv = *reinterpret_cast<const float4*>(&Vs[c][tx*4]);
            Oacc[0][0] = fmaf(p0,bv.x,Oacc[0][0]); Oacc[0][1] = fmaf(p0,bv.y,Oacc[0][1]);
            Oacc[0][2] = fmaf(p0,bv.z,Oacc[0][2]); Oacc[0][3] = fmaf(p0,bv.w,Oacc[0][3]);
            Oacc[1][0] = fmaf(p1,bv.x,Oacc[1][0]); Oacc[1][1] = fmaf(p1,bv.y,Oacc[1][1]);
            Oacc[1][2] = fmaf(p1,bv.z,Oacc[1][2]); Oacc[1][3] = fmaf(p1,bv.w,Oacc[1][3]);
            Oacc[2][0] = fmaf(p2,bv.x,Oacc[2][0]); Oacc[2][1] = fmaf(p2,bv.y,Oacc[2][1]);
            Oacc[2][2] = fmaf(p2,bv.z,Oacc[2][2]); Oacc[2][3] = fmaf(p2,bv.w,Oacc[2][3]);
            Oacc[3][0] = fmaf(p3,bv.x,Oacc[3][0]); Oacc[3][1] = fmaf(p3,bv.y,Oacc[3][1]);
            Oacc[3][2] = fmaf(p3,bv.z,Oacc[3][2]); Oacc[3][3] = fmaf(p3,bv.w,Oacc[3][3]);
        }
    }

    // Final normalize + store: ctx layout [B, S, H*DK]
    #pragma unroll
    for (int i = 0; i < 4; i++) {
        const float invl = 1.0f / lrun[i];
        const int r = ty*4 + i;
        float4 o;
        o.x = Oacc[i][0]*invl; o.y = Oacc[i][1]*invl;
        o.z = Oacc[i][2]*invl; o.w = Oacc[i][3]*invl;
        *reinterpret_cast<float4*>(O + baseQ + (size_t)r * DDIM + tx*4) = o;
    }
}

// ---------------------------------------------------------------------------
// Launch
// ---------------------------------------------------------------------------
extern "C" void kernel_launch(void* const* d_in, const int* in_sizes, int n_in,
                              void* d_out, int out_size)
{
    const float* x    = (const float*)d_in[0];
    const float* wq   = (const float*)d_in[1];
    const float* bq   = (const float*)d_in[2];
    const float* wk   = (const float*)d_in[3];
    const float* bk   = (const float*)d_in[4];
    const float* wv   = (const float*)d_in[5];
    const float* bv   = (const float*)d_in[6];
    const float* wo   = (const float*)d_in[7];
    const float* bo   = (const float*)d_in[8];
    const float* w1   = (const float*)d_in[9];
    const float* b1   = (const float*)d_in[10];
    const float* w2   = (const float*)d_in[11];
    const float* b2   = (const float*)d_in[12];
    const float* ln1a = (const float*)d_in[13];
    const float* ln1b = (const float*)d_in[14];
    const float* ln2a = (const float*)d_in[15];
    const float* ln2b = (const float*)d_in[16];
    float* out = (float*)d_out;

    float *xn, *q, *k, *v, *ctx, *h, *hn, *ff;
    cudaGetSymbolAddress((void**)&xn,  g_xn);
    cudaGetSymbolAddress((void**)&q,   g_q);
    cudaGetSymbolAddress((void**)&k,   g_k);
    cudaGetSymbolAddress((void**)&v,   g_v);
    cudaGetSymbolAddress((void**)&ctx, g_ctx);
    cudaGetSymbolAddress((void**)&h,   g_h);
    cudaGetSymbolAddress((void**)&hn,  g_hn);
    cudaGetSymbolAddress((void**)&ff,  g_ff);

    const dim3 gproj(DDIM/128, MTOT/128);   // (8, 32)
    const dim3 gffn1(FFD/128,  MTOT/128);   // (32, 32)

    ln_kernel<<<MTOT, 256>>>(x, ln1a, ln1b, xn);
    gemm_nt<<<gproj, 256>>>(xn, wq, bq, nullptr, q, MTOT, DDIM, DDIM, 0);
    gemm_nt<<<gproj, 256>>>(xn, wk, bk, nullptr, k, MTOT, DDIM, DDIM, 0);
    gemm_nt<<<gproj, 256>>>(xn, wv, bv, nullptr, v, MTOT, DDIM, DDIM, 0);
    attn_kernel<<<dim3(SS/64, BB*HH), 256>>>(q, k, v, ctx);
    gemm_nt<<<gproj, 256>>>(ctx, wo, bo, x, h, MTOT, DDIM, DDIM, 0);
    ln_kernel<<<MTOT, 256>>>(h, ln2a, ln2b, hn);
    gemm_nt<<<gffn1, 256>>>(hn, w1, b1, nullptr, ff, MTOT, FFD, DDIM, 1);
    gemm_nt<<<gproj, 256>>>(ff, w2, b2, h, out, MTOT, DDIM, FFD, 0);
}

// round 7
// speedup vs baseline: 1.8989x; 1.8989x over previous
#include <cuda_runtime.h>
#include <math.h>
#include <stdint.h>

// Problem constants
#define BB   2
#define SS   2048
#define DDIM 1024
#define HH   16
#define DK   64
#define FFD  4096
#define MTOT (BB*SS)   // 4096 rows

// ---------------------------------------------------------------------------
// Scratch buffers (device globals; no runtime allocation allowed)
// ---------------------------------------------------------------------------
__device__ float g_xn [MTOT*DDIM];
__device__ float g_q  [MTOT*DDIM];
__device__ float g_k  [MTOT*DDIM];
__device__ float g_v  [MTOT*DDIM];
__device__ float g_ctx[MTOT*DDIM];
__device__ float g_h  [MTOT*DDIM];
__device__ float g_hn [MTOT*DDIM];
__device__ float g_ff [MTOT*FFD];

// ---------------------------------------------------------------------------
// LayerNorm (faithful: unbiased std, denom = sqrt(std + eps))
// ---------------------------------------------------------------------------
__global__ __launch_bounds__(256) void ln_kernel(
    const float* __restrict__ x, const float* __restrict__ alpha,
    const float* __restrict__ beta, float* __restrict__ y)
{
    const int row = blockIdx.x;
    const float4* xr = reinterpret_cast<const float4*>(x + (size_t)row * DDIM);
    float4 vv = xr[threadIdx.x];
    float s  = vv.x + vv.y + vv.z + vv.w;
    float s2 = vv.x*vv.x + vv.y*vv.y + vv.z*vv.z + vv.w*vv.w;

    __shared__ float red0[8], red1[8];
    #pragma unroll
    for (int o = 16; o; o >>= 1) {
        s  += __shfl_xor_sync(0xffffffffu, s,  o);
        s2 += __shfl_xor_sync(0xffffffffu, s2, o);
    }
    const int warp = threadIdx.x >> 5, lane = threadIdx.x & 31;
    if (lane == 0) { red0[warp] = s; red1[warp] = s2; }
    __syncthreads();
    if (threadIdx.x == 0) {
        float t = 0.f, t2 = 0.f;
        #pragma unroll
        for (int i = 0; i < 8; i++) { t += red0[i]; t2 += red1[i]; }
        red0[0] = t; red1[0] = t2;
    }
    __syncthreads();
    s = red0[0]; s2 = red1[0];

    const float mean = s * (1.0f / DDIM);
    const float var  = fmaxf(0.f, (s2 - s * mean) * (1.0f / (DDIM - 1)));  // unbiased
    const float stdv = sqrtf(var);
    const float inv  = 1.0f / sqrtf(stdv + 1e-6f);   // sqrt(std + eps) !
    const float a0 = alpha[0], b0 = beta[0];

    float4 o;
    o.x = a0 * (vv.x - mean) * inv + b0;
    o.y = a0 * (vv.y - mean) * inv + b0;
    o.z = a0 * (vv.z - mean) * inv + b0;
    o.w = a0 * (vv.w - mean) * inv + b0;
    reinterpret_cast<float4*>(y + (size_t)row * DDIM)[threadIdx.x] = o;
}

// ---------------------------------------------------------------------------
// tf32 helpers
// ---------------------------------------------------------------------------
__device__ __forceinline__ uint32_t f2tf32(float x) {
    uint32_t r;
    asm("cvt.rna.tf32.f32 %0, %1;" : "=r"(r) : "f"(x));
    return r;
}

__device__ __forceinline__ void mma_tf32(
    float c[4], const uint32_t a[4], const uint32_t b[2])
{
    asm volatile(
        "mma.sync.aligned.m16n8k8.row.col.f32.tf32.tf32.f32 "
        "{%0,%1,%2,%3}, {%4,%5,%6,%7}, {%8,%9}, {%0,%1,%2,%3};\n"
        : "+f"(c[0]), "+f"(c[1]), "+f"(c[2]), "+f"(c[3])
        : "r"(a[0]), "r"(a[1]), "r"(a[2]), "r"(a[3]), "r"(b[0]), "r"(b[1]));
}

// ---------------------------------------------------------------------------
// Tensor-core GEMM (NT): C[M,N] = A[M,K]*W[N,K]^T + bias (+relu) (+res)
// CTA tile 128x128, K-tile 32. 8 warps as 2(m)x4(n); warp tile 64x32 via
// 4x4 grid of m16n8k8 tf32 mma. Fragment-major packed smem:
//   A: blk(mf*4+kc) stride 132 u32, within blk: lane*4 + pos (one LDS.128/frag)
//   B: blk(nf*4+kc) stride  66 u32, within blk: lane*2 + lo  (one LDS.64/frag)
// M,N multiples of 128; K multiple of 32.
// ---------------------------------------------------------------------------
__global__ __launch_bounds__(256, 2) void gemm_tc(
    const float* __restrict__ A, const float* __restrict__ W,
    const float* __restrict__ bias, const float* __restrict__ res,
    float* __restrict__ C, int M, int N, int K, int relu)
{
    __shared__ uint32_t As[32 * 132];   // 8 mf-blocks x 4 kc
    __shared__ uint32_t Bs[64 * 66];    // 16 nf-blocks x 4 kc

    const int tid  = threadIdx.x;
    const int lane = tid & 31;
    const int warp = tid >> 5;
    const int wm = warp >> 2;          // 0..1
    const int wn = warp & 3;           // 0..3
    const int g  = lane >> 2;          // 0..7
    const int t  = lane & 3;           // 0..3
    const int m0 = blockIdx.y * 128, n0 = blockIdx.x * 128;

    float acc[4][4][4];
    #pragma unroll
    for (int i = 0; i < 4; i++)
        #pragma unroll
        for (int j = 0; j < 4; j++)
            #pragma unroll
            for (int p = 0; p < 4; p++) acc[i][j][p] = 0.f;

    for (int k0 = 0; k0 < K; k0 += 32) {
        // ---- fill smem in fragment-major tf32 layout ----
        #pragma unroll
        for (int u = 0; u < 4; u++) {
            const int f  = tid + u * 256;       // 0..1023 float4 slots
            const int r  = f >> 3;              // 0..127
            const int kq = (f & 7) << 2;        // 0..28 step 4
            const int kc = kq >> 3;             // 0..3
            const int lo = (kq >> 2) & 1;       // 0/1

            // A
            {
                float4 a4 = *reinterpret_cast<const float4*>(
                    A + (size_t)(m0 + r) * K + k0 + kq);
                const int mf = r >> 4, gg = r & 7, hi = (r >> 3) & 1;
                uint32_t* d = As + (mf*4 + kc) * 132 + gg*16 + (hi + 2*lo);
                d[0]  = f2tf32(a4.x);
                d[4]  = f2tf32(a4.y);
                d[8]  = f2tf32(a4.z);
                d[12] = f2tf32(a4.w);
            }
            // B (W rows are output features n)
            {
                float4 b4 = *reinterpret_cast<const float4*>(
                    W + (size_t)(n0 + r) * K + k0 + kq);
                const int nf = r >> 3, gp = r & 7;
                uint32_t* d = Bs + (nf*4 + kc) * 66 + gp*8 + lo;
                d[0] = f2tf32(b4.x);
                d[2] = f2tf32(b4.y);
                d[4] = f2tf32(b4.z);
                d[6] = f2tf32(b4.w);
            }
        }
        __syncthreads();

        // ---- compute: 4 kc steps x 16 mma ----
        #pragma unroll
        for (int kc = 0; kc < 4; kc++) {
            uint32_t af[4][4];
            #pragma unroll
            for (int mf = 0; mf < 4; mf++) {
                const uint4 v = *reinterpret_cast<const uint4*>(
                    As + ((wm*4 + mf)*4 + kc) * 132 + lane*4);
                af[mf][0] = v.x; af[mf][1] = v.y; af[mf][2] = v.z; af[mf][3] = v.w;
            }
            uint32_t bf[4][2];
            #pragma unroll
            for (int nf = 0; nf < 4; nf++) {
                const uint2 v = *reinterpret_cast<const uint2*>(
                    Bs + ((wn*4 + nf)*4 + kc) * 66 + lane*2);
                bf[nf][0] = v.x; bf[nf][1] = v.y;
            }
            #pragma unroll
            for (int mf = 0; mf < 4; mf++)
                #pragma unroll
                for (int nf = 0; nf < 4; nf++)
                    mma_tf32(acc[mf][nf], af[mf], bf[nf]);
        }
        __syncthreads();
    }

    // ---- epilogue: bias (+relu) (+res), float2 stores ----
    #pragma unroll
    for (int mf = 0; mf < 4; mf++) {
        const int row = m0 + wm*64 + mf*16 + g;
        #pragma unroll
        for (int nf = 0; nf < 4; nf++) {
            const int col = n0 + wn*32 + nf*8 + t*2;
            const float2 bi = *reinterpret_cast<const float2*>(bias + col);
            float2 c0, c1;
            c0.x = acc[mf][nf][0] + bi.x; c0.y = acc[mf][nf][1] + bi.y;
            c1.x = acc[mf][nf][2] + bi.x; c1.y = acc[mf][nf][3] + bi.y;
            if (relu) {
                c0.x = fmaxf(c0.x, 0.f); c0.y = fmaxf(c0.y, 0.f);
                c1.x = fmaxf(c1.x, 0.f); c1.y = fmaxf(c1.y, 0.f);
            }
            const size_t b0 = (size_t)row * N + col;
            const size_t b1 = (size_t)(row + 8) * N + col;
            if (res) {
                const float2 r0 = *reinterpret_cast<const float2*>(res + b0);
                const float2 r1 = *reinterpret_cast<const float2*>(res + b1);
                c0.x += r0.x; c0.y += r0.y;
                c1.x += r1.x; c1.y += r1.y;
            }
            *reinterpret_cast<float2*>(C + b0) = c0;
            *reinterpret_cast<float2*>(C + b1) = c1;
        }
    }
}

// ---------------------------------------------------------------------------
// Flash attention, fp32 (unchanged from passing round)
// ---------------------------------------------------------------------------
__global__ __launch_bounds__(256, 2) void attn_kernel(
    const float* __restrict__ Q, const float* __restrict__ K,
    const float* __restrict__ V, float* __restrict__ O)
{
    __shared__ float Qs[64][64];
    __shared__ float Vs[64][64];
    __shared__ float KP[64][64];   // K^T (swizzled) during S-gemm; P afterwards

    const int tid = threadIdx.x;
    const int tx = tid & 15, ty = tid >> 4;
    const int qb = blockIdx.x;
    const int bh = blockIdx.y;
    const int b  = bh >> 4, h = bh & 15;

    const size_t baseQ  = ((size_t)b * SS + (size_t)qb * 64) * DDIM + (size_t)h * DK;
    const size_t baseKV = (size_t)b * SS * DDIM + (size_t)h * DK;

    #pragma unroll
    for (int u = 0; u < 4; u++) {
        const int f = tid + u * 256;
        const int r = f >> 4, cq = (f & 15) << 2;
        *reinterpret_cast<float4*>(&Qs[r][cq]) =
            *reinterpret_cast<const float4*>(Q + baseQ + (size_t)r * DDIM + cq);
    }

    float Oacc[4][4];
    float mrun[4], lrun[4];
    #pragma unroll
    for (int i = 0; i < 4; i++) {
        mrun[i] = -INFINITY; lrun[i] = 0.f;
        #pragma unroll
        for (int j = 0; j < 4; j++) Oacc[i][j] = 0.f;
    }

    for (int kv0 = 0; kv0 < SS; kv0 += 64) {
        __syncthreads();
        #pragma unroll
        for (int u = 0; u < 4; u++) {
            const int f = tid + u * 256;
            const int n = f >> 4, cq = (f & 15) << 2;
            float4 kt = *reinterpret_cast<const float4*>(K + baseKV + (size_t)(kv0 + n) * DDIM + cq);
            KP[cq+0][n ^ ((cq+0) & 31)] = kt.x;
            KP[cq+1][n ^ ((cq+1) & 31)] = kt.y;
            KP[cq+2][n ^ ((cq+2) & 31)] = kt.z;
            KP[cq+3][n ^ ((cq+3) & 31)] = kt.w;
            *reinterpret_cast<float4*>(&Vs[n][cq]) =
                *reinterpret_cast<const float4*>(V + baseKV + (size_t)(kv0 + n) * DDIM + cq);
        }
        __syncthreads();

        float Sv[4][4];
        #pragma unroll
        for (int i = 0; i < 4; i++)
            #pragma unroll
            for (int j = 0; j < 4; j++) Sv[i][j] = 0.f;

        #pragma unroll 8
        for (int c = 0; c < 64; c++) {
            const int sw = c & 31, t4 = tx * 4;
            float a0 = Qs[ty*4+0][c], a1 = Qs[ty*4+1][c];
            float a2 = Qs[ty*4+2][c], a3 = Qs[ty*4+3][c];
            float b0 = KP[c][(t4+0) ^ sw], b1 = KP[c][(t4+1) ^ sw];
            float b2 = KP[c][(t4+2) ^ sw], b3 = KP[c][(t4+3) ^ sw];
            Sv[0][0] = fmaf(a0,b0,Sv[0][0]); Sv[0][1] = fmaf(a0,b1,Sv[0][1]);
            Sv[0][2] = fmaf(a0,b2,Sv[0][2]); Sv[0][3] = fmaf(a0,b3,Sv[0][3]);
            Sv[1][0] = fmaf(a1,b0,Sv[1][0]); Sv[1][1] = fmaf(a1,b1,Sv[1][1]);
            Sv[1][2] = fmaf(a1,b2,Sv[1][2]); Sv[1][3] = fmaf(a1,b3,Sv[1][3]);
            Sv[2][0] = fmaf(a2,b0,Sv[2][0]); Sv[2][1] = fmaf(a2,b1,Sv[2][1]);
            Sv[2][2] = fmaf(a2,b2,Sv[2][2]); Sv[2][3] = fmaf(a2,b3,Sv[2][3]);
            Sv[3][0] = fmaf(a3,b0,Sv[3][0]); Sv[3][1] = fmaf(a3,b1,Sv[3][1]);
            Sv[3][2] = fmaf(a3,b2,Sv[3][2]); Sv[3][3] = fmaf(a3,b3,Sv[3][3]);
        }

        #pragma unroll
        for (int i = 0; i < 4; i++) {
            float rm = -INFINITY;
            #pragma unroll
            for (int j = 0; j < 4; j++) {
                Sv[i][j] *= 0.125f;
                rm = fmaxf(rm, Sv[i][j]);
            }
            #pragma unroll
            for (int o = 8; o; o >>= 1)
                rm = fmaxf(rm, __shfl_xor_sync(0xffffffffu, rm, o));
            const float mn = fmaxf(mrun[i], rm);
            const float corr = __expf(mrun[i] - mn);
            mrun[i] = mn;
            float rs = 0.f;
            #pragma unroll
            for (int j = 0; j < 4; j++) {
                const float p = __expf(Sv[i][j] - mn);
                Sv[i][j] = p; rs += p;
            }
            #pragma unroll
            for (int o = 8; o; o >>= 1)
                rs += __shfl_xor_sync(0xffffffffu, rs, o);
            lrun[i] = lrun[i] * corr + rs;
            #pragma unroll
            for (int j = 0; j < 4; j++) Oacc[i][j] *= corr;
        }

        __syncthreads();
        #pragma unroll
        for (int i = 0; i < 4; i++)
            #pragma unroll
            for (int j = 0; j < 4; j++)
                KP[ty*4 + i][tx*4 + j] = Sv[i][j];
        __syncthreads();

        #pragma unroll 8
        for (int c = 0; c < 64; c++) {
            float p0 = KP[ty*4+0][c], p1 = KP[ty*4+1][c];
            float p2 = KP[ty*4+2][c], p3 = KP[ty*4+3][c];
            float4 bv = *reinterpret_cast<const float4*>(&Vs[c][tx*4]);
            Oacc[0][0] = fmaf(p0,bv.x,Oacc[0][0]); Oacc[0][1] = fmaf(p0,bv.y,Oacc[0][1]);
            Oacc[0][2] = fmaf(p0,bv.z,Oacc[0][2]); Oacc[0][3] = fmaf(p0,bv.w,Oacc[0][3]);
            Oacc[1][0] = fmaf(p1,bv.x,Oacc[1][0]); Oacc[1][1] = fmaf(p1,bv.y,Oacc[1][1]);
            Oacc[1][2] = fmaf(p1,bv.z,Oacc[1][2]); Oacc[1][3] = fmaf(p1,bv.w,Oacc[1][3]);
            Oacc[2][0] = fmaf(p2,bv.x,Oacc[2][0]); Oacc[2][1] = fmaf(p2,bv.y,Oacc[2][1]);
            Oacc[2][2] = fmaf(p2,bv.z,Oacc[2][2]); Oacc[2][3] = fmaf(p2,bv.w,Oacc[2][3]);
            Oacc[3][0] = fmaf(p3,bv.x,Oacc[3][0]); Oacc[3][1] = fmaf(p3,bv.y,Oacc[3][1]);
            Oacc[3][2] = fmaf(p3,bv.z,Oacc[3][2]); Oacc[3][3] = fmaf(p3,bv.w,Oacc[3][3]);
        }
    }

    #pragma unroll
    for (int i = 0; i < 4; i++) {
        const float invl = 1.0f / lrun[i];
        const int r = ty*4 + i;
        float4 o;
        o.x = Oacc[i][0]*invl; o.y = Oacc[i][1]*invl;
        o.z = Oacc[i][2]*invl; o.w = Oacc[i][3]*invl;
        *reinterpret_cast<float4*>(O + baseQ + (size_t)r * DDIM + tx*4) = o;
    }
}

// ---------------------------------------------------------------------------
// Launch
// ---------------------------------------------------------------------------
extern "C" void kernel_launch(void* const* d_in, const int* in_sizes, int n_in,
                              void* d_out, int out_size)
{
    const float* x    = (const float*)d_in[0];
    const float* wq   = (const float*)d_in[1];
    const float* bq   = (const float*)d_in[2];
    const float* wk   = (const float*)d_in[3];
    const float* bk   = (const float*)d_in[4];
    const float* wv   = (const float*)d_in[5];
    const float* bv   = (const float*)d_in[6];
    const float* wo   = (const float*)d_in[7];
    const float* bo   = (const float*)d_in[8];
    const float* w1   = (const float*)d_in[9];
    const float* b1   = (const float*)d_in[10];
    const float* w2   = (const float*)d_in[11];
    const float* b2   = (const float*)d_in[12];
    const float* ln1a = (const float*)d_in[13];
    const float* ln1b = (const float*)d_in[14];
    const float* ln2a = (const float*)d_in[15];
    const float* ln2b = (const float*)d_in[16];
    float* out = (float*)d_out;

    float *xn, *q, *k, *v, *ctx, *h, *hn, *ff;
    cudaGetSymbolAddress((void**)&xn,  g_xn);
    cudaGetSymbolAddress((void**)&q,   g_q);
    cudaGetSymbolAddress((void**)&k,   g_k);
    cudaGetSymbolAddress((void**)&v,   g_v);
    cudaGetSymbolAddress((void**)&ctx, g_ctx);
    cudaGetSymbolAddress((void**)&h,   g_h);
    cudaGetSymbolAddress((void**)&hn,  g_hn);
    cudaGetSymbolAddress((void**)&ff,  g_ff);

    const dim3 gproj(DDIM/128, MTOT/128);   // (8, 32)
    const dim3 gffn1(FFD/128,  MTOT/128);   // (32, 32)

    ln_kernel<<<MTOT, 256>>>(x, ln1a, ln1b, xn);
    gemm_tc<<<gproj, 256>>>(xn, wq, bq, nullptr, q, MTOT, DDIM, DDIM, 0);
    gemm_tc<<<gproj, 256>>>(xn, wk, bk, nullptr, k, MTOT, DDIM, DDIM, 0);
    gemm_tc<<<gproj, 256>>>(xn, wv, bv, nullptr, v, MTOT, DDIM, DDIM, 0);
    attn_kernel<<<dim3(SS/64, BB*HH), 256>>>(q, k, v, ctx);
    gemm_tc<<<gproj, 256>>>(ctx, wo, bo, x, h, MTOT, DDIM, DDIM, 0);
    ln_kernel<<<MTOT, 256>>>(h, ln2a, ln2b, hn);
    gemm_tc<<<gffn1, 256>>>(hn, w1, b1, nullptr, ff, MTOT, FFD, DDIM, 1);
    gemm_tc<<<gproj, 256>>>(ff, w2, b2, h, out, MTOT, DDIM, FFD, 0);
}

// round 8
// speedup vs baseline: 2.9194x; 1.5374x over previous
#include <cuda_runtime.h>
#include <math.h>
#include <stdint.h>

// Problem constants
#define BB   2
#define SS   2048
#define DDIM 1024
#define HH   16
#define DK   64
#define FFD  4096
#define MTOT (BB*SS)   // 4096 rows

// ---------------------------------------------------------------------------
// Scratch buffers (device globals; no runtime allocation allowed)
// ---------------------------------------------------------------------------
__device__ float g_xn [MTOT*DDIM];
__device__ float g_q  [MTOT*DDIM];
__device__ float g_k  [MTOT*DDIM];
__device__ float g_v  [MTOT*DDIM];
__device__ float g_ctx[MTOT*DDIM];
__device__ float g_h  [MTOT*DDIM];
__device__ float g_hn [MTOT*DDIM];
__device__ float g_ff [MTOT*FFD];

// ---------------------------------------------------------------------------
// LayerNorm (faithful: unbiased std, denom = sqrt(std + eps))
// ---------------------------------------------------------------------------
__global__ __launch_bounds__(256) void ln_kernel(
    const float* __restrict__ x, const float* __restrict__ alpha,
    const float* __restrict__ beta, float* __restrict__ y)
{
    const int row = blockIdx.x;
    const float4* xr = reinterpret_cast<const float4*>(x + (size_t)row * DDIM);
    float4 vv = xr[threadIdx.x];
    float s  = vv.x + vv.y + vv.z + vv.w;
    float s2 = vv.x*vv.x + vv.y*vv.y + vv.z*vv.z + vv.w*vv.w;

    __shared__ float red0[8], red1[8];
    #pragma unroll
    for (int o = 16; o; o >>= 1) {
        s  += __shfl_xor_sync(0xffffffffu, s,  o);
        s2 += __shfl_xor_sync(0xffffffffu, s2, o);
    }
    const int warp = threadIdx.x >> 5, lane = threadIdx.x & 31;
    if (lane == 0) { red0[warp] = s; red1[warp] = s2; }
    __syncthreads();
    if (threadIdx.x == 0) {
        float t = 0.f, t2 = 0.f;
        #pragma unroll
        for (int i = 0; i < 8; i++) { t += red0[i]; t2 += red1[i]; }
        red0[0] = t; red1[0] = t2;
    }
    __syncthreads();
    s = red0[0]; s2 = red1[0];

    const float mean = s * (1.0f / DDIM);
    const float var  = fmaxf(0.f, (s2 - s * mean) * (1.0f / (DDIM - 1)));  // unbiased
    const float stdv = sqrtf(var);
    const float inv  = 1.0f / sqrtf(stdv + 1e-6f);   // sqrt(std + eps) !
    const float a0 = alpha[0], b0 = beta[0];

    float4 o;
    o.x = a0 * (vv.x - mean) * inv + b0;
    o.y = a0 * (vv.y - mean) * inv + b0;
    o.z = a0 * (vv.z - mean) * inv + b0;
    o.w = a0 * (vv.w - mean) * inv + b0;
    reinterpret_cast<float4*>(y + (size_t)row * DDIM)[threadIdx.x] = o;
}

// ---------------------------------------------------------------------------
// tf32 helpers
// ---------------------------------------------------------------------------
__device__ __forceinline__ uint32_t f2tf32(float x) {
    uint32_t r;
    asm("cvt.rna.tf32.f32 %0, %1;" : "=r"(r) : "f"(x));
    return r;
}

__device__ __forceinline__ void mma_tf32(
    float c[4], const uint32_t a[4], const uint32_t b[2])
{
    asm volatile(
        "mma.sync.aligned.m16n8k8.row.col.f32.tf32.tf32.f32 "
        "{%0,%1,%2,%3}, {%4,%5,%6,%7}, {%8,%9}, {%0,%1,%2,%3};\n"
        : "+f"(c[0]), "+f"(c[1]), "+f"(c[2]), "+f"(c[3])
        : "r"(a[0]), "r"(a[1]), "r"(a[2]), "r"(a[3]), "r"(b[0]), "r"(b[1]));
}

// ---------------------------------------------------------------------------
// Tensor-core GEMM (NT): C[M,N] = A[M,K]*W[N,K]^T + bias (+relu) (+res)
// (unchanged from passing round 7)
// ---------------------------------------------------------------------------
__global__ __launch_bounds__(256, 2) void gemm_tc(
    const float* __restrict__ A, const float* __restrict__ W,
    const float* __restrict__ bias, const float* __restrict__ res,
    float* __restrict__ C, int M, int N, int K, int relu)
{
    __shared__ uint32_t As[32 * 132];   // 8 mf-blocks x 4 kc
    __shared__ uint32_t Bs[64 * 66];    // 16 nf-blocks x 4 kc

    const int tid  = threadIdx.x;
    const int lane = tid & 31;
    const int warp = tid >> 5;
    const int wm = warp >> 2;          // 0..1
    const int wn = warp & 3;           // 0..3
    const int g  = lane >> 2;          // 0..7
    const int t  = lane & 3;           // 0..3
    const int m0 = blockIdx.y * 128, n0 = blockIdx.x * 128;

    float acc[4][4][4];
    #pragma unroll
    for (int i = 0; i < 4; i++)
        #pragma unroll
        for (int j = 0; j < 4; j++)
            #pragma unroll
            for (int p = 0; p < 4; p++) acc[i][j][p] = 0.f;

    for (int k0 = 0; k0 < K; k0 += 32) {
        #pragma unroll
        for (int u = 0; u < 4; u++) {
            const int f  = tid + u * 256;
            const int r  = f >> 3;
            const int kq = (f & 7) << 2;
            const int kc = kq >> 3;
            const int lo = (kq >> 2) & 1;

            {
                float4 a4 = *reinterpret_cast<const float4*>(
                    A + (size_t)(m0 + r) * K + k0 + kq);
                const int mf = r >> 4, gg = r & 7, hi = (r >> 3) & 1;
                uint32_t* d = As + (mf*4 + kc) * 132 + gg*16 + (hi + 2*lo);
                d[0]  = f2tf32(a4.x);
                d[4]  = f2tf32(a4.y);
                d[8]  = f2tf32(a4.z);
                d[12] = f2tf32(a4.w);
            }
            {
                float4 b4 = *reinterpret_cast<const float4*>(
                    W + (size_t)(n0 + r) * K + k0 + kq);
                const int nf = r >> 3, gp = r & 7;
                uint32_t* d = Bs + (nf*4 + kc) * 66 + gp*8 + lo;
                d[0] = f2tf32(b4.x);
                d[2] = f2tf32(b4.y);
                d[4] = f2tf32(b4.z);
                d[6] = f2tf32(b4.w);
            }
        }
        __syncthreads();

        #pragma unroll
        for (int kc = 0; kc < 4; kc++) {
            uint32_t af[4][4];
            #pragma unroll
            for (int mf = 0; mf < 4; mf++) {
                const uint4 v = *reinterpret_cast<const uint4*>(
                    As + ((wm*4 + mf)*4 + kc) * 132 + lane*4);
                af[mf][0] = v.x; af[mf][1] = v.y; af[mf][2] = v.z; af[mf][3] = v.w;
            }
            uint32_t bf[4][2];
            #pragma unroll
            for (int nf = 0; nf < 4; nf++) {
                const uint2 v = *reinterpret_cast<const uint2*>(
                    Bs + ((wn*4 + nf)*4 + kc) * 66 + lane*2);
                bf[nf][0] = v.x; bf[nf][1] = v.y;
            }
            #pragma unroll
            for (int mf = 0; mf < 4; mf++)
                #pragma unroll
                for (int nf = 0; nf < 4; nf++)
                    mma_tf32(acc[mf][nf], af[mf], bf[nf]);
        }
        __syncthreads();
    }

    #pragma unroll
    for (int mf = 0; mf < 4; mf++) {
        const int row = m0 + wm*64 + mf*16 + g;
        #pragma unroll
        for (int nf = 0; nf < 4; nf++) {
            const int col = n0 + wn*32 + nf*8 + t*2;
            const float2 bi = *reinterpret_cast<const float2*>(bias + col);
            float2 c0, c1;
            c0.x = acc[mf][nf][0] + bi.x; c0.y = acc[mf][nf][1] + bi.y;
            c1.x = acc[mf][nf][2] + bi.x; c1.y = acc[mf][nf][3] + bi.y;
            if (relu) {
                c0.x = fmaxf(c0.x, 0.f); c0.y = fmaxf(c0.y, 0.f);
                c1.x = fmaxf(c1.x, 0.f); c1.y = fmaxf(c1.y, 0.f);
            }
            const size_t b0 = (size_t)row * N + col;
            const size_t b1 = (size_t)(row + 8) * N + col;
            if (res) {
                const float2 r0 = *reinterpret_cast<const float2*>(res + b0);
                const float2 r1 = *reinterpret_cast<const float2*>(res + b1);
                c0.x += r0.x; c0.y += r0.y;
                c1.x += r1.x; c1.y += r1.y;
            }
            *reinterpret_cast<float2*>(C + b0) = c0;
            *reinterpret_cast<float2*>(C + b1) = c1;
        }
    }
}

// ---------------------------------------------------------------------------
// Tensor-core flash attention (tf32 mma, fp32 accum, fp32 online softmax).
// Br=Bc=64, 4 warps x 16 q-rows. Q fragments in registers (1/8 scale folded).
// K,V fragment-major smem (1 LDS.64 per B fragment). P round-trips through
// smem aliased over the K buffer. smem total ~34.3KB.
// ---------------------------------------------------------------------------
__global__ __launch_bounds__(128, 2) void attn_tc(
    const float* __restrict__ Q, const float* __restrict__ K,
    const float* __restrict__ V, float* __restrict__ O)
{
    __shared__ uint32_t Vs [64 * 66];   // V fragment-major (k=kv, n=d)
    __shared__ uint32_t KPs[64 * 68];   // union: K frag-major (4224 u32) / Qtmp / P row-major

    const int tid  = threadIdx.x;
    const int lane = tid & 31;
    const int w    = tid >> 5;          // warp 0..3 -> q rows w*16..w*16+15
    const int g    = lane >> 2;         // 0..7
    const int t    = lane & 3;          // 0..3
    const int qb   = blockIdx.x;        // 0..31
    const int bh   = blockIdx.y;        // 0..31
    const int b    = bh >> 4, h = bh & 15;

    const size_t baseQ  = ((size_t)b * SS + (size_t)qb * 64) * DDIM + (size_t)h * DK;
    const size_t baseKV = (size_t)b * SS * DDIM + (size_t)h * DK;

    // ---- stage Q tile row-major into KPs, then lift fragments to registers ----
    {
        float* qt = reinterpret_cast<float*>(KPs);
        #pragma unroll
        for (int u = 0; u < 8; u++) {
            const int f = tid + u * 128;         // 64 rows x 16 float4
            const int r = f >> 4, cq = (f & 15) << 2;
            *reinterpret_cast<float4*>(qt + r*68 + cq) =
                *reinterpret_cast<const float4*>(Q + baseQ + (size_t)r * DDIM + cq);
        }
    }
    __syncthreads();

    uint32_t aq[8][4];
    {
        const float* qt = reinterpret_cast<const float*>(KPs);
        const int r0 = w*16 + g, r1 = r0 + 8;
        #pragma unroll
        for (int kc = 0; kc < 8; kc++) {
            aq[kc][0] = f2tf32(0.125f * qt[r0*68 + kc*8 + t]);
            aq[kc][1] = f2tf32(0.125f * qt[r1*68 + kc*8 + t]);
            aq[kc][2] = f2tf32(0.125f * qt[r0*68 + kc*8 + t + 4]);
            aq[kc][3] = f2tf32(0.125f * qt[r1*68 + kc*8 + t + 4]);
        }
    }

    float Of[8][4];
    float m0 = -INFINITY, m1 = -INFINITY, l0 = 0.f, l1 = 0.f;
    #pragma unroll
    for (int nf = 0; nf < 8; nf++)
        #pragma unroll
        for (int p = 0; p < 4; p++) Of[nf][p] = 0.f;

    for (int kv0 = 0; kv0 < SS; kv0 += 64) {
        __syncthreads();   // Q staging / previous tile's P+V reads complete

        // ---- fill K (frag-major, n=kv rows, k=d) and V (frag-major, k=kv, n=d) ----
        #pragma unroll
        for (int u = 0; u < 8; u++) {
            const int f = tid + u * 128;
            const int r = f >> 4;               // 0..63 (kv row)
            const int kq = (f & 15) << 2;       // 0..60 step 4 (d col)

            // K: exactly the gemm B layout, 8 kc blocks
            {
                float4 kv4 = *reinterpret_cast<const float4*>(
                    K + baseKV + (size_t)(kv0 + r) * DDIM + kq);
                const int kc = kq >> 3, lo = (kq >> 2) & 1;
                const int nf = r >> 3, gp = r & 7;
                uint32_t* d = KPs + (nf*8 + kc) * 66 + gp*8 + lo;
                d[0] = f2tf32(kv4.x);
                d[2] = f2tf32(kv4.y);
                d[4] = f2tf32(kv4.z);
                d[6] = f2tf32(kv4.w);
            }
            // V: transposed fragment roles (k = kv = r, n = d = col)
            {
                float4 vv4 = *reinterpret_cast<const float4*>(
                    V + baseKV + (size_t)(kv0 + r) * DDIM + kq);
                const int kc = r >> 3, kt = r & 7;
                const int tt = kt & 3, e = kt >> 2;
                const int nf = kq >> 3, gn = kq & 7;   // gn in {0,4}
                uint32_t* d = Vs + (nf*8 + kc) * 66 + (gn*4 + tt)*2 + e;
                d[0]  = f2tf32(vv4.x);
                d[8]  = f2tf32(vv4.y);
                d[16] = f2tf32(vv4.z);
                d[24] = f2tf32(vv4.w);
            }
        }
        __syncthreads();

        // ---- S = (Q/8) K^T : 64 mma per warp ----
        float Sf[8][4];
        #pragma unroll
        for (int nf = 0; nf < 8; nf++)
            #pragma unroll
            for (int p = 0; p < 4; p++) Sf[nf][p] = 0.f;

        #pragma unroll
        for (int kc = 0; kc < 8; kc++) {
            #pragma unroll
            for (int nf = 0; nf < 8; nf++) {
                const uint2 v = *reinterpret_cast<const uint2*>(
                    KPs + (nf*8 + kc) * 66 + lane*2);
                uint32_t bf[2] = { v.x, v.y };
                mma_tf32(Sf[nf], aq[kc], bf);
            }
        }

        // ---- online softmax (rows g and g+8 of this warp's 16-row block) ----
        float mx0 = -INFINITY, mx1 = -INFINITY;
        #pragma unroll
        for (int nf = 0; nf < 8; nf++) {
            mx0 = fmaxf(mx0, fmaxf(Sf[nf][0], Sf[nf][1]));
            mx1 = fmaxf(mx1, fmaxf(Sf[nf][2], Sf[nf][3]));
        }
        #pragma unroll
        for (int o = 1; o <= 2; o <<= 1) {
            mx0 = fmaxf(mx0, __shfl_xor_sync(0xffffffffu, mx0, o));
            mx1 = fmaxf(mx1, __shfl_xor_sync(0xffffffffu, mx1, o));
        }
        const float mn0 = fmaxf(m0, mx0), mn1 = fmaxf(m1, mx1);
        const float c0 = __expf(m0 - mn0), c1 = __expf(m1 - mn1);
        m0 = mn0; m1 = mn1;

        float s0 = 0.f, s1 = 0.f;
        #pragma unroll
        for (int nf = 0; nf < 8; nf++) {
            float p0 = __expf(Sf[nf][0] - mn0);
            float p1 = __expf(Sf[nf][1] - mn0);
            float p2 = __expf(Sf[nf][2] - mn1);
            float p3 = __expf(Sf[nf][3] - mn1);
            Sf[nf][0] = p0; Sf[nf][1] = p1; Sf[nf][2] = p2; Sf[nf][3] = p3;
            s0 += p0 + p1; s1 += p2 + p3;
        }
        #pragma unroll
        for (int o = 1; o <= 2; o <<= 1) {
            s0 += __shfl_xor_sync(0xffffffffu, s0, o);
            s1 += __shfl_xor_sync(0xffffffffu, s1, o);
        }
        l0 = l0 * c0 + s0;
        l1 = l1 * c1 + s1;
        #pragma unroll
        for (int nf = 0; nf < 8; nf++) {
            Of[nf][0] *= c0; Of[nf][1] *= c0;
            Of[nf][2] *= c1; Of[nf][3] *= c1;
        }

        // ---- P -> smem (aliased over K; all warps must be done with K) ----
        __syncthreads();
        float* Pw = reinterpret_cast<float*>(KPs) + (w*16) * 68;
        #pragma unroll
        for (int nf = 0; nf < 8; nf++) {
            Pw[g*68     + nf*8 + 2*t    ] = Sf[nf][0];
            Pw[g*68     + nf*8 + 2*t + 1] = Sf[nf][1];
            Pw[(g+8)*68 + nf*8 + 2*t    ] = Sf[nf][2];
            Pw[(g+8)*68 + nf*8 + 2*t + 1] = Sf[nf][3];
        }
        __syncwarp();

        // ---- O += P V : 64 mma per warp ----
        #pragma unroll
        for (int kc = 0; kc < 8; kc++) {
            uint32_t ap[4];
            ap[0] = f2tf32(Pw[g*68     + kc*8 + t    ]);
            ap[1] = f2tf32(Pw[(g+8)*68 + kc*8 + t    ]);
            ap[2] = f2tf32(Pw[g*68     + kc*8 + t + 4]);
            ap[3] = f2tf32(Pw[(g+8)*68 + kc*8 + t + 4]);
            #pragma unroll
            for (int nf = 0; nf < 8; nf++) {
                const uint2 v = *reinterpret_cast<const uint2*>(
                    Vs + (nf*8 + kc) * 66 + lane*2);
                uint32_t bf[2] = { v.x, v.y };
                mma_tf32(Of[nf], ap, bf);
            }
        }
    }

    // ---- finalize: divide by l, store to ctx [B,S,D] head slice ----
    const float inv0 = 1.0f / l0, inv1 = 1.0f / l1;
    const int r0 = w*16 + g, r1 = r0 + 8;
    #pragma unroll
    for (int nf = 0; nf < 8; nf++) {
        const int col = nf*8 + 2*t;
        float2 o0, o1;
        o0.x = Of[nf][0] * inv0; o0.y = Of[nf][1] * inv0;
        o1.x = Of[nf][2] * inv1; o1.y = Of[nf][3] * inv1;
        *reinterpret_cast<float2*>(O + baseQ + (size_t)r0 * DDIM + col) = o0;
        *reinterpret_cast<float2*>(O + baseQ + (size_t)r1 * DDIM + col) = o1;
    }
}

// ---------------------------------------------------------------------------
// Launch
// ---------------------------------------------------------------------------
extern "C" void kernel_launch(void* const* d_in, const int* in_sizes, int n_in,
                              void* d_out, int out_size)
{
    const float* x    = (const float*)d_in[0];
    const float* wq   = (const float*)d_in[1];
    const float* bq   = (const float*)d_in[2];
    const float* wk   = (const float*)d_in[3];
    const float* bk   = (const float*)d_in[4];
    const float* wv   = (const float*)d_in[5];
    const float* bv   = (const float*)d_in[6];
    const float* wo   = (const float*)d_in[7];
    const float* bo   = (const float*)d_in[8];
    const float* w1   = (const float*)d_in[9];
    const float* b1   = (const float*)d_in[10];
    const float* w2   = (const float*)d_in[11];
    const float* b2   = (const float*)d_in[12];
    const float* ln1a = (const float*)d_in[13];
    const float* ln1b = (const float*)d_in[14];
    const float* ln2a = (const float*)d_in[15];
    const float* ln2b = (const float*)d_in[16];
    float* out = (float*)d_out;

    float *xn, *q, *k, *v, *ctx, *h, *hn, *ff;
    cudaGetSymbolAddress((void**)&xn,  g_xn);
    cudaGetSymbolAddress((void**)&q,   g_q);
    cudaGetSymbolAddress((void**)&k,   g_k);
    cudaGetSymbolAddress((void**)&v,   g_v);
    cudaGetSymbolAddress((void**)&ctx, g_ctx);
    cudaGetSymbolAddress((void**)&h,   g_h);
    cudaGetSymbolAddress((void**)&hn,  g_hn);
    cudaGetSymbolAddress((void**)&ff,  g_ff);

    const dim3 gproj(DDIM/128, MTOT/128);   // (8, 32)
    const dim3 gffn1(FFD/128,  MTOT/128);   // (32, 32)

    ln_kernel<<<MTOT, 256>>>(x, ln1a, ln1b, xn);
    gemm_tc<<<gproj, 256>>>(xn, wq, bq, nullptr, q, MTOT, DDIM, DDIM, 0);
    gemm_tc<<<gproj, 256>>>(xn, wk, bk, nullptr, k, MTOT, DDIM, DDIM, 0);
    gemm_tc<<<gproj, 256>>>(xn, wv, bv, nullptr, v, MTOT, DDIM, DDIM, 0);
    attn_tc<<<dim3(SS/64, BB*HH), 128>>>(q, k, v, ctx);
    gemm_tc<<<gproj, 256>>>(ctx, wo, bo, x, h, MTOT, DDIM, DDIM, 0);
    ln_kernel<<<MTOT, 256>>>(h, ln2a, ln2b, hn);
    gemm_tc<<<gffn1, 256>>>(hn, w1, b1, nullptr, ff, MTOT, FFD, DDIM, 1);
    gemm_tc<<<gproj, 256>>>(ff, w2, b2, h, out, MTOT, DDIM, FFD, 0);
}